// round 1
// baseline (speedup 1.0000x reference)
#include <cuda_runtime.h>

#define BB   32
#define NN   2048
#define KK   16
#define FIN  32
#define FOUT 64
#define NPTS (BB * NN)   // 65536

// Scratch (allocation-free rule: __device__ globals)
__device__ float g_a[NPTS * FOUT];    // x @ (W1 - W2) + b_edge
__device__ float g_c[NPTS * FOUT];    // x @ W2
__device__ float g_s[NPTS * FOUT];    // relu(x @ W_nn + b_nn)
__device__ int   g_idx[NPTS * KK];    // global neighbor indices

// ---------------------------------------------------------------------------
// Kernel 1: kNN. One block per 512 points, whole batch's positions in SMEM.
// Thread-per-point top-16 via guarded register insertion sort.
// ---------------------------------------------------------------------------
__global__ __launch_bounds__(512) void knn_kernel(const float* __restrict__ pos) {
    __shared__ float4 sp[NN];   // 32 KB

    const int b    = blockIdx.x >> 2;         // 4 blocks per batch
    const int base = b * NN;
    const int tid  = threadIdx.x;

    for (int j = tid; j < NN; j += 512) {
        const float* p = pos + (size_t)(base + j) * 3;
        sp[j] = make_float4(p[0], p[1], p[2], 0.f);
    }
    __syncthreads();

    const int il = ((blockIdx.x & 3) << 9) + tid;   // local point index
    const float4 me = sp[il];

    float dk[KK];
    int   ik[KK];
#pragma unroll
    for (int k = 0; k < KK; k++) { dk[k] = 3.0e38f; ik[k] = 0; }

#pragma unroll 4
    for (int j = 0; j < NN; j++) {
        float4 q = sp[j];
        float dx = me.x - q.x;
        float dy = me.y - q.y;
        float dz = me.z - q.z;
        float d2 = fmaf(dx, dx, fmaf(dy, dy, dz * dz));
        if (j == il) d2 = 3.0e38f;          // exclude self (strict < excludes)
        if (d2 < dk[KK - 1]) {
            dk[KK - 1] = d2; ik[KK - 1] = j;
#pragma unroll
            for (int k = KK - 1; k > 0; --k) {
                if (dk[k] < dk[k - 1]) {
                    float td = dk[k]; dk[k] = dk[k - 1]; dk[k - 1] = td;
                    int   ti = ik[k]; ik[k] = ik[k - 1]; ik[k - 1] = ti;
                }
            }
        }
    }

    const int gi = base + il;
#pragma unroll
    for (int k = 0; k < KK; k++) g_idx[gi * KK + k] = base + ik[k];
}

// ---------------------------------------------------------------------------
// Kernel 2: per-node transforms. a = x@(W1-W2)+b_e, c = x@W2, s = relu(x@Wn+bn)
// Weights in SMEM (float4 loads), x row in registers. 128 threads = 128 nodes.
// ---------------------------------------------------------------------------
__global__ __launch_bounds__(128) void transform_kernel(
    const float* __restrict__ x,
    const float* __restrict__ We,   // (2*FIN, FOUT)
    const float* __restrict__ be,   // (FOUT)
    const float* __restrict__ Wn,   // (FIN, FOUT)
    const float* __restrict__ bn)   // (FOUT)
{
    __shared__ float s_wd[FIN * FOUT];   // W1 - W2
    __shared__ float s_w2[FIN * FOUT];
    __shared__ float s_wn[FIN * FOUT];
    __shared__ float s_be[FOUT];
    __shared__ float s_bn[FOUT];

    const int tid = threadIdx.x;
    for (int t = tid; t < FIN * FOUT; t += 128) {
        float w2 = We[FIN * FOUT + t];
        s_w2[t] = w2;
        s_wd[t] = We[t] - w2;
        s_wn[t] = Wn[t];
    }
    if (tid < FOUT) { s_be[tid] = be[tid]; s_bn[tid] = bn[tid]; }
    __syncthreads();

    const int node = blockIdx.x * 128 + tid;

    float xr[FIN];
#pragma unroll
    for (int r = 0; r < FIN; r += 4) {
        float4 v = *reinterpret_cast<const float4*>(x + (size_t)node * FIN + r);
        xr[r] = v.x; xr[r + 1] = v.y; xr[r + 2] = v.z; xr[r + 3] = v.w;
    }

    for (int f0 = 0; f0 < FOUT; f0 += 4) {
        float a0 = s_be[f0], a1 = s_be[f0 + 1], a2 = s_be[f0 + 2], a3 = s_be[f0 + 3];
        float c0 = 0.f, c1 = 0.f, c2 = 0.f, c3 = 0.f;
        float k0 = s_bn[f0], k1 = s_bn[f0 + 1], k2 = s_bn[f0 + 2], k3 = s_bn[f0 + 3];
#pragma unroll
        for (int r = 0; r < FIN; r++) {
            float xv = xr[r];
            float4 wd = *reinterpret_cast<const float4*>(&s_wd[r * FOUT + f0]);
            float4 w2 = *reinterpret_cast<const float4*>(&s_w2[r * FOUT + f0]);
            float4 wn = *reinterpret_cast<const float4*>(&s_wn[r * FOUT + f0]);
            a0 = fmaf(xv, wd.x, a0); a1 = fmaf(xv, wd.y, a1);
            a2 = fmaf(xv, wd.z, a2); a3 = fmaf(xv, wd.w, a3);
            c0 = fmaf(xv, w2.x, c0); c1 = fmaf(xv, w2.y, c1);
            c2 = fmaf(xv, w2.z, c2); c3 = fmaf(xv, w2.w, c3);
            k0 = fmaf(xv, wn.x, k0); k1 = fmaf(xv, wn.y, k1);
            k2 = fmaf(xv, wn.z, k2); k3 = fmaf(xv, wn.w, k3);
        }
        size_t o = (size_t)node * FOUT + f0;
        *reinterpret_cast<float4*>(&g_a[o]) = make_float4(a0, a1, a2, a3);
        *reinterpret_cast<float4*>(&g_c[o]) = make_float4(c0, c1, c2, c3);
        *reinterpret_cast<float4*>(&g_s[o]) = make_float4(fmaxf(k0, 0.f), fmaxf(k1, 0.f),
                                                          fmaxf(k2, 0.f), fmaxf(k3, 0.f));
    }
}

// ---------------------------------------------------------------------------
// Kernel 3: aggregation. Thread per (node, feature).
// out = relu(max_k (a_i + c_{nbr_k})) + s_i  ;  relu∘max == max∘relu.
// ---------------------------------------------------------------------------
__global__ __launch_bounds__(256) void aggregate_kernel(float* __restrict__ out) {
    const int gid = blockIdx.x * 256 + threadIdx.x;   // gid == i*FOUT + f
    const int i = gid >> 6;
    const int f = gid & 63;

    int jj[KK];
#pragma unroll
    for (int k = 0; k < KK; k++) jj[k] = g_idx[i * KK + k];   // broadcast loads

    float cv[KK];
#pragma unroll
    for (int k = 0; k < KK; k++) cv[k] = g_c[(size_t)jj[k] * FOUT + f];  // coalesced

    float m = cv[0];
#pragma unroll
    for (int k = 1; k < KK; k++) m = fmaxf(m, cv[k]);

    float af = g_a[gid];
    float sv = g_s[gid];
    out[gid] = fmaxf(m + af, 0.f) + sv;
}

// ---------------------------------------------------------------------------
extern "C" void kernel_launch(void* const* d_in, const int* in_sizes, int n_in,
                              void* d_out, int out_size) {
    const float* x   = (const float*)d_in[0];
    const float* pos = (const float*)d_in[1];
    const float* We  = (const float*)d_in[2];
    const float* be  = (const float*)d_in[3];
    const float* Wn  = (const float*)d_in[4];
    const float* bn  = (const float*)d_in[5];
    // d_in[6] = batch (implied by layout; unused)
    float* out = (float*)d_out;

    knn_kernel<<<NPTS / 512, 512>>>(pos);
    transform_kernel<<<NPTS / 128, 128>>>(x, We, be, Wn, bn);
    aggregate_kernel<<<(NPTS * FOUT) / 256, 256>>>(out);
}